// round 4
// baseline (speedup 1.0000x reference)
#include <cuda_runtime.h>
#include <math.h>

#define BSZ 1024      // batch (edge events)
#define NND 1024      // nodes
#define DIM 256       // feature dim
#define K3  768       // 3*DIM

// ---------------- scratch (device globals; no allocation) ----------------
__device__ float g_Xsrc[BSZ * K3];
__device__ float g_Xtar[BSZ * K3];
__device__ float g_H0[BSZ * DIM];
__device__ float g_H1[BSZ * DIM];
__device__ float g_M0[BSZ * DIM];
__device__ float g_M1[BSZ * DIM];
__device__ float g_sums[NND * DIM];
__device__ float g_cnt[NND];
__device__ float g_GI[NND * K3];
__device__ float g_GH[NND * K3];

// ---------------- kernels ----------------

__global__ void init_kernel() {
    int i = blockIdx.x * blockDim.x + threadIdx.x;
    if (i < NND * DIM) g_sums[i] = 0.0f;
    if (i < NND) g_cnt[i] = 0.0f;
}

// One block per batch element, 256 threads (one per feature dim).
__global__ void gather_kernel(const float* __restrict__ memory,
                              const int* __restrict__ src,
                              const int* __restrict__ tgt,
                              const float* __restrict__ dtv) {
    int b = blockIdx.x;
    int t = threadIdx.x;
    int s = src[b];
    int g = tgt[b];
    float vms = memory[(size_t)s * DIM + t];
    float vmg = memory[(size_t)g * DIM + t];
    float ds = dtv[((size_t)b * NND + s) * DIM + t];
    float dg = dtv[((size_t)b * NND + g) * DIM + t];
    size_t row = (size_t)b * K3;
    g_Xsrc[row + t]           = vms;
    g_Xsrc[row + DIM + t]     = vmg;
    g_Xsrc[row + 2 * DIM + t] = ds;
    g_Xtar[row + t]           = vmg;
    g_Xtar[row + DIM + t]     = vms;
    g_Xtar[row + 2 * DIM + t] = dg;
    if (t == 0) {
        atomicAdd(&g_cnt[s], 1.0f);
        atomicAdd(&g_cnt[g], 1.0f);
    }
}

// Batched (z in {0,1}) tiled SGEMM: C[M,N] = A[M,K] @ W[N,K]^T + bias[N], optional relu.
// BM=BN=64, BK=16, 256 threads, 4x4 per-thread microtile. M,N mult of 64; K mult of 16.
struct GemmArgs {
    const float* A;
    const float* W;
    const float* bias;
    float* C;
};

__global__ __launch_bounds__(256) void sgemm_kernel(GemmArgs a0, GemmArgs a1,
                                                    int M, int N, int K, int relu) {
    __shared__ float As[64][17];
    __shared__ float Ws[64][17];

    GemmArgs ga = (blockIdx.z == 0) ? a0 : a1;
    const float* __restrict__ A = ga.A;
    const float* __restrict__ W = ga.W;

    int bm = blockIdx.y * 64;
    int bn = blockIdx.x * 64;
    int tx = threadIdx.x;       // 0..255
    int tr = tx >> 4;           // 0..15
    int tc = tx & 15;           // 0..15

    float acc[4][4];
#pragma unroll
    for (int i = 0; i < 4; i++)
#pragma unroll
        for (int j = 0; j < 4; j++) acc[i][j] = 0.0f;

    for (int k0 = 0; k0 < K; k0 += 16) {
#pragma unroll
        for (int i = 0; i < 4; i++) {
            int idx = tx + i * 256;       // 0..1023
            int r = idx >> 4;             // 0..63
            int c = idx & 15;             // 0..15
            As[r][c] = A[(size_t)(bm + r) * K + k0 + c];
            Ws[r][c] = W[(size_t)(bn + r) * K + k0 + c];
        }
        __syncthreads();
#pragma unroll
        for (int kk = 0; kk < 16; kk++) {
            float av[4], wv[4];
#pragma unroll
            for (int i = 0; i < 4; i++) av[i] = As[tr * 4 + i][kk];
#pragma unroll
            for (int j = 0; j < 4; j++) wv[j] = Ws[tc * 4 + j][kk];
#pragma unroll
            for (int i = 0; i < 4; i++)
#pragma unroll
                for (int j = 0; j < 4; j++) acc[i][j] = fmaf(av[i], wv[j], acc[i][j]);
        }
        __syncthreads();
    }

#pragma unroll
    for (int i = 0; i < 4; i++) {
        int r = bm + tr * 4 + i;
#pragma unroll
        for (int j = 0; j < 4; j++) {
            int c = bn + tc * 4 + j;
            float v = acc[i][j] + ga.bias[c];
            if (relu) v = fmaxf(v, 0.0f);
            ga.C[(size_t)r * N + c] = v;
        }
    }
}

// One block per message row (2B rows), 256 threads.
__global__ void scatter_kernel(const int* __restrict__ src,
                               const int* __restrict__ tgt) {
    int i = blockIdx.x;   // 0..2B-1
    int t = threadIdx.x;
    int node;
    const float* msg;
    if (i < BSZ) {
        node = src[i];
        msg = g_M0 + (size_t)i * DIM;
    } else {
        node = tgt[i - BSZ];
        msg = g_M1 + (size_t)(i - BSZ) * DIM;
    }
    atomicAdd(&g_sums[(size_t)node * DIM + t], msg[t]);
}

__global__ void aggdiv_kernel() {
    int i = blockIdx.x * blockDim.x + threadIdx.x;  // NND*DIM
    int n = i >> 8;  // /DIM
    float c = g_cnt[n];
    g_sums[i] = g_sums[i] / fmaxf(c, 1.0f);
}

// One block per node, 256 threads (one per dim).
__global__ void gru_kernel(const float* __restrict__ memory,
                           float* __restrict__ out) {
    int n = blockIdx.x;
    int d = threadIdx.x;
    size_t row = (size_t)n * K3;
    float ir = g_GI[row + d];
    float iz = g_GI[row + DIM + d];
    float in_ = g_GI[row + 2 * DIM + d];
    float hr = g_GH[row + d];
    float hz = g_GH[row + DIM + d];
    float hn = g_GH[row + 2 * DIM + d];
    float h = memory[(size_t)n * DIM + d];
    float r = 1.0f / (1.0f + expf(-(ir + hr)));
    float z = 1.0f / (1.0f + expf(-(iz + hz)));
    float nn = tanhf(in_ + r * hn);
    float nv = (1.0f - z) * nn + z * h;
    out[(size_t)n * DIM + d] = (g_cnt[n] > 0.0f) ? nv : h;
}

// ---------------- host ----------------

extern "C" void kernel_launch(void* const* d_in, const int* in_sizes, int n_in,
                              void* d_out, int out_size) {
    const float* memory   = (const float*)d_in[0];
    const int*   source   = (const int*)d_in[1];
    const int*   target   = (const int*)d_in[2];
    const float* dtv      = (const float*)d_in[3];
    const float* src_w1   = (const float*)d_in[4];
    const float* src_b1   = (const float*)d_in[5];
    const float* src_w2   = (const float*)d_in[6];
    const float* src_b2   = (const float*)d_in[7];
    const float* tar_w1   = (const float*)d_in[8];
    const float* tar_b1   = (const float*)d_in[9];
    const float* tar_w2   = (const float*)d_in[10];
    const float* tar_b2   = (const float*)d_in[11];
    const float* gru_wih  = (const float*)d_in[12];
    const float* gru_whh  = (const float*)d_in[13];
    const float* gru_bih  = (const float*)d_in[14];
    const float* gru_bhh  = (const float*)d_in[15];
    float* out = (float*)d_out;

    // Resolve scratch symbol addresses once (first call = correctness run,
    // happens before graph capture).
    static float *pXsrc = nullptr, *pXtar, *pH0, *pH1, *pM0, *pM1, *pSums, *pGI, *pGH;
    if (!pXsrc) {
        cudaGetSymbolAddress((void**)&pXsrc, g_Xsrc);
        cudaGetSymbolAddress((void**)&pXtar, g_Xtar);
        cudaGetSymbolAddress((void**)&pH0,   g_H0);
        cudaGetSymbolAddress((void**)&pH1,   g_H1);
        cudaGetSymbolAddress((void**)&pM0,   g_M0);
        cudaGetSymbolAddress((void**)&pM1,   g_M1);
        cudaGetSymbolAddress((void**)&pSums, g_sums);
        cudaGetSymbolAddress((void**)&pGI,   g_GI);
        cudaGetSymbolAddress((void**)&pGH,   g_GH);
    }

    // 1. zero sums + counts
    init_kernel<<<(NND * DIM + 255) / 256, 256>>>();

    // 2. gather MLP inputs + counts
    gather_kernel<<<BSZ, 256>>>(memory, source, target, dtv);

    // 3. hidden = relu(X @ W1^T + b1)   [M=1024, N=256, K=768], batched src/tar
    {
        GemmArgs a0{pXsrc, src_w1, src_b1, pH0};
        GemmArgs a1{pXtar, tar_w1, tar_b1, pH1};
        dim3 grid(DIM / 64, BSZ / 64, 2);
        sgemm_kernel<<<grid, 256>>>(a0, a1, BSZ, DIM, K3, 1);
    }

    // 4. msg = hidden @ W2^T + b2       [M=1024, N=256, K=256], batched src/tar
    {
        GemmArgs a0{pH0, src_w2, src_b2, pM0};
        GemmArgs a1{pH1, tar_w2, tar_b2, pM1};
        dim3 grid(DIM / 64, BSZ / 64, 2);
        sgemm_kernel<<<grid, 256>>>(a0, a1, BSZ, DIM, DIM, 0);
    }

    // 5. scatter-add messages into segment sums
    scatter_kernel<<<2 * BSZ, 256>>>(source, target);

    // 6. agg = sums / max(cnt, 1)
    aggdiv_kernel<<<(NND * DIM) / 256, 256>>>();

    // 7. GI = agg @ wih^T + bih ; GH = memory @ whh^T + bhh  [M=1024, N=768, K=256]
    {
        GemmArgs a0{pSums, gru_wih, gru_bih, pGI};
        GemmArgs a1{memory, gru_whh, gru_bhh, pGH};
        dim3 grid(K3 / 64, NND / 64, 2);
        sgemm_kernel<<<grid, 256>>>(a0, a1, NND, K3, DIM, 0);
    }

    // 8. GRU elementwise + touched mask
    gru_kernel<<<NND, 256>>>(memory, out);
}